// round 7
// baseline (speedup 1.0000x reference)
#include <cuda_runtime.h>

#define KMAX  21
#define GNUM  20
#define PAIRS 11     // 11 k-pairs cover 21 planes (pair 10 high lane = junk)
#define TILE  512
#define BT    384    // 12 warps
#define GRID  296
#define EPSF  1e-6f

__device__ float g_A[KMAX * GNUM];   // A[k*GNUM + g]
__device__ int   g_count;

__global__ void ms_init_kernel() {
    int t = threadIdx.x;
    if (t < KMAX * GNUM) g_A[t] = 0.0f;
    if (t == 0) g_count = 0;
}

// A[k,g] = sum_p d[p][k]*gt[g][p], d = log(p+eps)-log(1-p+eps).
// argmin_g ce[k,g] == argmax_g A[k,g] (log(1-p) term constant over g).
__global__ __launch_bounds__(BT, 2) void ms_accum_kernel(
    const void* bufA, const void* bufB, int n, float* __restrict__ out)
{
    __shared__ __align__(16) float sd[TILE * KMAX + 32];  // +pad for k=21 junk read
    __shared__ __align__(16) unsigned smask[TILE];
    __shared__ int s_last;

    const int tid  = threadIdx.x;
    const int lane = tid & 31;
    const int wid  = tid >> 5;

    // ---- inline buffer-identity probe (gt words are {0,1}) ----
    const unsigned wA = ((const unsigned*)bufA)[lane];
    const bool a_is_gt = (__ballot_sync(0xffffffffu, wA > 1u) == 0u);
    const float* seg = (const float*)(a_is_gt ? bufB : bufA);  // (N,21) f32
    const int*   gtp = (const int*)  (a_is_gt ? bufA : bufB);  // (21,N) {0,1}

    // ---- perfectly balanced contiguous chunk per block (4-aligned) ----
    int begin = (int)(((long long)blockIdx.x * n) / GRID) & ~3;
    int end   = (int)(((long long)(blockIdx.x + 1) * n) / GRID) & ~3;
    if (blockIdx.x == GRID - 1) end = n;

    unsigned long long acc2[GNUM];
    #pragma unroll
    for (int g = 0; g < GNUM; g++) acc2[g] = 0ULL;

    for (int base = begin; base < end; base += TILE) {
        const int cnt = min(TILE, end - base);

        // ---- phase 1: masks (int4 gt loads, 4 pixels/thread) ----
        const int cnt4 = cnt >> 2;
        for (int q = tid; q < cnt4; q += BT) {
            unsigned m0 = 0, m1 = 0, m2 = 0, m3 = 0;
            #pragma unroll
            for (int g = 0; g < GNUM; g++) {
                const uint4 v = __ldg(
                    (const uint4*)(gtp + (long long)g * n + base) + q);
                m0 |= ((unsigned)v.x) << g;
                m1 |= ((unsigned)v.y) << g;
                m2 |= ((unsigned)v.z) << g;
                m3 |= ((unsigned)v.w) << g;
            }
            ((uint4*)smask)[q] = make_uint4(m0, m1, m2, m3);
        }
        for (int p = (cnt4 << 2) + tid; p < cnt; p += BT) {   // generic remainder
            unsigned m = 0;
            #pragma unroll
            for (int g = 0; g < GNUM; g++)
                m |= (__ldg(gtp + (long long)g * n + base + p) != 0 ? 1u : 0u) << g;
            smask[p] = m;
        }

        // ---- phase 1: seg -> d into smem (linear float4 copy) ----
        {
            const float4* src = (const float4*)(seg + (long long)base * KMAX);
            float4* dst = (float4*)sd;
            const int t4 = (cnt * KMAX) >> 2;  // cnt mult of 4 -> exact
            for (int i = tid; i < t4; i += BT) {
                float4 v = __ldg(src + i);
                float4 o;
                o.x = __logf(v.x + EPSF) - __logf(1.0f - v.x + EPSF);
                o.y = __logf(v.y + EPSF) - __logf(1.0f - v.y + EPSF);
                o.z = __logf(v.z + EPSF) - __logf(1.0f - v.z + EPSF);
                o.w = __logf(v.w + EPSF) - __logf(1.0f - v.w + EPSF);
                dst[i] = o;
            }
            for (int i = (t4 << 2) + tid; i < cnt * KMAX; i += BT) {  // remainder
                float p = __ldg(seg + (long long)base * KMAX + i);
                sd[i] = __logf(p + EPSF) - __logf(1.0f - p + EPSF);
            }
        }
        __syncthreads();

        // ---- phase 2: warp = k-pair, f32x2 packed predicated adds ----
        if (wid < PAIRS) {
            const int k0 = 2 * wid;
            if (cnt == TILE) {
                #pragma unroll
                for (int j = 0; j < TILE / 32; j++) {
                    const int p = lane + 32 * j;
                    const float dlo = sd[p * KMAX + k0];
                    const float dhi = sd[p * KMAX + k0 + 1]; // pair10: junk, ignored
                    unsigned long long d2;
                    asm("mov.b64 %0, {%1, %2};" : "=l"(d2) : "f"(dlo), "f"(dhi));
                    const unsigned m = smask[p];
                    #pragma unroll
                    for (int g = 0; g < GNUM; g++) {
                        asm volatile(
                            "{ .reg .pred p;\n\t"
                            "setp.ne.u32 p, %2, 0;\n\t"
                            "@p add.rn.f32x2 %0, %0, %1; }"
                            : "+l"(acc2[g]) : "l"(d2), "r"(m & (1u << g)));
                    }
                }
            } else {
                for (int p = lane; p < cnt; p += 32) {
                    const float dlo = sd[p * KMAX + k0];
                    const float dhi = sd[p * KMAX + k0 + 1];
                    unsigned long long d2;
                    asm("mov.b64 %0, {%1, %2};" : "=l"(d2) : "f"(dlo), "f"(dhi));
                    const unsigned m = smask[p];
                    #pragma unroll
                    for (int g = 0; g < GNUM; g++) {
                        asm volatile(
                            "{ .reg .pred p;\n\t"
                            "setp.ne.u32 p, %2, 0;\n\t"
                            "@p add.rn.f32x2 %0, %0, %1; }"
                            : "+l"(acc2[g]) : "l"(d2), "r"(m & (1u << g)));
                    }
                }
            }
        }
        __syncthreads();
    }

    // ---- per-warp reduce + one atomic per (k,g) per block ----
    if (wid < PAIRS) {
        #pragma unroll
        for (int g = 0; g < GNUM; g++) {
            unsigned ulo, uhi;
            asm("mov.b64 {%0, %1}, %2;" : "=r"(ulo), "=r"(uhi) : "l"(acc2[g]));
            float flo = __uint_as_float(ulo);
            float fhi = __uint_as_float(uhi);
            #pragma unroll
            for (int off = 16; off > 0; off >>= 1) {
                flo += __shfl_xor_sync(0xffffffffu, flo, off);
                fhi += __shfl_xor_sync(0xffffffffu, fhi, off);
            }
            if (lane == 0) {
                atomicAdd(&g_A[(2 * wid) * GNUM + g], flo);
                if (wid < PAIRS - 1)
                    atomicAdd(&g_A[(2 * wid + 1) * GNUM + g], fhi);
            }
        }
    }

    // ---- last block finalizes (ticket) ----
    __threadfence();
    __syncthreads();
    if (tid == 0)
        s_last = (atomicAdd(&g_count, 1) == GRID - 1) ? 1 : 0;
    __syncthreads();
    if (s_last && tid < KMAX) {
        const volatile float* A = g_A;
        float best = A[tid * GNUM + 0];
        int bi = 0;
        #pragma unroll
        for (int g = 1; g < GNUM; g++) {
            float v = A[tid * GNUM + g];
            if (v > best) { best = v; bi = g; }  // FIRST max == first min of ce
        }
        out[tid] = (float)bi;   // output compared as float32
    }
}

extern "C" void kernel_launch(void* const* d_in, const int* in_sizes, int n_in,
                              void* d_out, int out_size) {
    int maxSize = 0;
    for (int i = 0; i < n_in; i++)
        if (in_sizes[i] > maxSize) maxSize = in_sizes[i];
    int idxA = -1, idxB = -1;
    for (int i = 0; i < n_in; i++) {
        if (in_sizes[i] == maxSize) {
            if (idxA < 0) idxA = i;
            else if (idxB < 0) idxB = i;
        }
    }
    if (idxB < 0) idxB = idxA;

    const void* bufA = d_in[idxA];
    const void* bufB = d_in[idxB];
    const int n = maxSize / KMAX;
    float* out = (float*)d_out;

    ms_init_kernel<<<1, 512>>>();
    ms_accum_kernel<<<GRID, BT>>>(bufA, bufB, n, out);
    (void)out_size;
}